// round 15
// baseline (speedup 1.0000x reference)
#include <cuda_runtime.h>
#include <cuda_fp16.h>
#include <cstdint>

// ---------------------------------------------------------------------------
// SelfAttention: B=4, S=2048, IN_C=256, HEADS=8, head_dim=256, HID_C=256
// R15: R14 + attn inner loops fused: QK(i) k-chunks interleaved with PV(i-1)
// k-chunks (two independent MMA dependency chains per warp -> tensor pipe
// stays fed across LDSM latency). Everything else unchanged.
// ---------------------------------------------------------------------------

#define BATCH 4
#define SEQ   2048
#define INC   256
#define HEADS 8
#define NQK   (INC*HEADS)
#define ROWS_TOTAL (BATCH*SEQ)
#define SM_SCALE 0.17677669529663687f
#define LOG2E    1.4426950408889634f
#define CCF      (SM_SCALE*LOG2E)
#define ONES2    0x3C003C00u           // half2(1,1)

__device__ __half g_Q[(size_t)BATCH*HEADS*SEQ*INC];
__device__ __half g_K[(size_t)BATCH*HEADS*SEQ*INC];
__device__ __half g_V[(size_t)BATCH*HEADS*SEQ*INC];
__device__ __half g_U[(size_t)ROWS_TOTAL*NQK];
__device__ __half g_Xh[(size_t)ROWS_TOTAL*INC];
__device__ __half g_WQh[(size_t)INC*NQK];
__device__ __half g_WKh[(size_t)INC*NQK];
__device__ __half g_WVh[(size_t)INC*NQK];
__device__ __half g_Wouth[(size_t)NQK*INC];

__device__ __forceinline__ void mma16816(float c[4],
    uint32_t a0, uint32_t a1, uint32_t a2, uint32_t a3,
    uint32_t b0, uint32_t b1)
{
    asm volatile(
        "mma.sync.aligned.m16n8k16.row.col.f32.f16.f16.f32 "
        "{%0,%1,%2,%3}, {%4,%5,%6,%7}, {%8,%9}, {%0,%1,%2,%3};\n"
        : "+f"(c[0]), "+f"(c[1]), "+f"(c[2]), "+f"(c[3])
        : "r"(a0), "r"(a1), "r"(a2), "r"(a3), "r"(b0), "r"(b1));
}
__device__ __forceinline__ void ldsm4a(uint32_t r[4], uint32_t a) {
    asm volatile("ldmatrix.sync.aligned.m8n8.x4.shared.b16 {%0,%1,%2,%3}, [%4];"
        : "=r"(r[0]), "=r"(r[1]), "=r"(r[2]), "=r"(r[3]) : "r"(a));
}
__device__ __forceinline__ void ldsm4ta(uint32_t r[4], uint32_t a) {
    asm volatile("ldmatrix.sync.aligned.m8n8.x4.trans.shared.b16 {%0,%1,%2,%3}, [%4];"
        : "=r"(r[0]), "=r"(r[1]), "=r"(r[2]), "=r"(r[3]) : "r"(a));
}
__device__ __forceinline__ void stsm4a(uint32_t a, uint32_t r0, uint32_t r1,
                                       uint32_t r2, uint32_t r3) {
    asm volatile("stmatrix.sync.aligned.m8n8.x4.shared.b16 [%0], {%1,%2,%3,%4};"
        :: "r"(a), "r"(r0), "r"(r1), "r"(r2), "r"(r3) : "memory");
}
__device__ __forceinline__ uint32_t pack_ex2(float a, float b) {
    __half2 h = __floats2half2_rn(a, b);
    uint32_t u = reinterpret_cast<uint32_t&>(h);
    asm volatile("ex2.approx.f16x2 %0, %0;" : "+r"(u));
    return u;
}
__device__ __forceinline__ uint32_t packh2(float a, float b) {
    __half2 h = __floats2half2_rn(a, b);
    return reinterpret_cast<uint32_t&>(h);
}
__device__ __forceinline__ uint4 lds128a(uint32_t a) {
    uint4 v;
    asm volatile("ld.shared.v4.b32 {%0,%1,%2,%3}, [%4];"
        : "=r"(v.x), "=r"(v.y), "=r"(v.z), "=r"(v.w) : "r"(a));
    return v;
}

#define CPA16A(dsta, src) \
    asm volatile("cp.async.cg.shared.global [%0], [%1], 16;" :: "r"(dsta), "l"(src))
#define CP_COMMIT() asm volatile("cp.async.commit_group;")
#define CP_WAIT0()  asm volatile("cp.async.wait_group 0;")
#define CP_WAIT1()  asm volatile("cp.async.wait_group 1;")

__device__ __forceinline__ uint32_t swz512(int row, int cb) {
    return (uint32_t)(row*512 + (cb ^ ((row & 7) << 4)));
}
__device__ __forceinline__ uint32_t swz256(int row, int cb) {
    return (uint32_t)(row*256 + (cb ^ ((row & 7) << 4)));
}
__device__ __forceinline__ uint32_t swz128(int row, int cb) {
    return (uint32_t)(row*128 + (cb ^ ((row & 7) << 4)));
}

// ---------------------------------------------------------------------------
// Fused f32 -> f16 convert for all 5 tensors
// ---------------------------------------------------------------------------
#define CVT_NX   (ROWS_TOTAL*INC/8)
#define CVT_NW   (INC*NQK/8)
#define CVT_TOTAL (CVT_NX + 4*CVT_NW)

__global__ void __launch_bounds__(256) cvt_all_kernel(
    const float4* __restrict__ v,  const float4* __restrict__ wq,
    const float4* __restrict__ wk, const float4* __restrict__ wv,
    const float4* __restrict__ wo)
{
    int i = blockIdx.x * 256 + threadIdx.x;
    if (i >= CVT_TOTAL) return;
    const float4* src; uint4* dst; int off;
    if (i < CVT_NX)               { src = v;  dst = (uint4*)g_Xh;    off = i; }
    else if (i < CVT_NX+CVT_NW)   { src = wq; dst = (uint4*)g_WQh;   off = i - CVT_NX; }
    else if (i < CVT_NX+2*CVT_NW) { src = wk; dst = (uint4*)g_WKh;   off = i - CVT_NX - CVT_NW; }
    else if (i < CVT_NX+3*CVT_NW) { src = wv; dst = (uint4*)g_WVh;   off = i - CVT_NX - 2*CVT_NW; }
    else                          { src = wo; dst = (uint4*)g_Wouth; off = i - CVT_NX - 3*CVT_NW; }
    float4 a = src[2*off], b = src[2*off+1];
    uint4 o;
    o.x = packh2(a.x, a.y); o.y = packh2(a.z, a.w);
    o.z = packh2(b.x, b.y); o.w = packh2(b.z, b.w);
    dst[off] = o;
}

// ---------------------------------------------------------------------------
// Projection GEMM (f16): BM=128 BN=128 BK=64, double-buffered.
// Epilogue: stmatrix-stage C in smem, coalesced uint4 writes.
// ---------------------------------------------------------------------------
#define GB_A 0
#define GB_B 32768
#define GEMM_SMEM 65536

__global__ void __launch_bounds__(256) proj_kernel()
{
    extern __shared__ __align__(1024) char smc[];
    const uint32_t sb = (uint32_t)__cvta_generic_to_shared(smc);
    const int tid  = threadIdx.x;
    const int lane = tid & 31, warp = tid >> 5;
    const int wm = warp >> 1, wn = warp & 1;
    const int lr = lane & 7, lb = (lane >> 3) & 1, lc = lane >> 4;
    const int jr = lane & 15, jc = lane >> 4;
    const int bx = blockIdx.x, by = blockIdx.y, which = blockIdx.z;
    const __half* W = (which == 0) ? g_WQh : (which == 1) ? g_WKh : g_WVh;
    const __half* X = g_Xh;

    auto loadA = [&](int buf, int kb) {
#pragma unroll
        for (int p = 0; p < 4; ++p) {
            int idx = tid + p*256;
            int r = idx >> 3, cb = (idx & 7) * 16;
            CPA16A(sb + GB_A + (uint32_t)buf*16384 + swz128(r, cb),
                   X + (size_t)(by*128 + r)*256 + kb*64 + (idx & 7)*8);
        }
    };
    auto loadB = [&](int buf, int kb) {
#pragma unroll
        for (int p = 0; p < 4; ++p) {
            int idx = tid + p*256;
            int r = idx >> 4, cb = (idx & 15) * 16;
            CPA16A(sb + GB_B + (uint32_t)buf*16384 + swz256(r, cb),
                   W + (size_t)(kb*64 + r)*2048 + bx*128 + (idx & 15)*8);
        }
    };

    float acc[2][8][4];
#pragma unroll
    for (int a = 0; a < 2; a++)
#pragma unroll
        for (int b = 0; b < 8; b++)
#pragma unroll
            for (int c = 0; c < 4; c++) acc[a][b][c] = 0.f;

    loadA(0, 0); loadB(0, 0); CP_COMMIT();

    for (int kb = 0; kb < 4; ++kb) {
        const int cur = kb & 1;
        if (kb + 1 < 4) { loadA(cur ^ 1, kb + 1); loadB(cur ^ 1, kb + 1); CP_COMMIT(); }
        if (kb + 1 < 4) { CP_WAIT1(); } else { CP_WAIT0(); }
        __syncthreads();

        const uint32_t abase = sb + GB_A + (uint32_t)cur*16384;
        const uint32_t bbase = sb + GB_B + (uint32_t)cur*16384;
#pragma unroll
        for (int kk = 0; kk < 64; kk += 16) {
            uint32_t A[2][4];
#pragma unroll
            for (int mt = 0; mt < 2; ++mt)
                ldsm4a(A[mt], abase + swz128(wm*32 + mt*16 + lr + lb*8, kk*2 + lc*16));
#pragma unroll
            for (int ntp = 0; ntp < 4; ++ntp) {
                uint32_t B[4];
                ldsm4ta(B, bbase + swz256(kk + lr + lb*8, wn*128 + ntp*32 + lc*16));
                mma16816(acc[0][2*ntp],   A[0][0],A[0][1],A[0][2],A[0][3], B[0],B[1]);
                mma16816(acc[0][2*ntp+1], A[0][0],A[0][1],A[0][2],A[0][3], B[2],B[3]);
                mma16816(acc[1][2*ntp],   A[1][0],A[1][1],A[1][2],A[1][3], B[0],B[1]);
                mma16816(acc[1][2*ntp+1], A[1][0],A[1][1],A[1][2],A[1][3], B[2],B[3]);
            }
        }
        __syncthreads();
    }

    const float sc = (which == 0) ? CCF : 1.f;
    const uint32_t cs = sb + GB_A;
#pragma unroll
    for (int mt = 0; mt < 2; ++mt) {
#pragma unroll
        for (int ntp = 0; ntp < 4; ++ntp) {
            uint32_t e01 = packh2(acc[mt][2*ntp][0]*sc,   acc[mt][2*ntp][1]*sc);
            uint32_t e23 = packh2(acc[mt][2*ntp][2]*sc,   acc[mt][2*ntp][3]*sc);
            uint32_t o01 = packh2(acc[mt][2*ntp+1][0]*sc, acc[mt][2*ntp+1][1]*sc);
            uint32_t o23 = packh2(acc[mt][2*ntp+1][2]*sc, acc[mt][2*ntp+1][3]*sc);
            stsm4a(cs + swz256(wm*32 + mt*16 + jr, wn*128 + ntp*32 + jc*16),
                   e01, e23, o01, o23);
        }
    }
    __syncthreads();

    __half* Out = (which == 0) ? g_Q : (which == 1) ? g_K : g_V;
    {
        const int r = tid >> 1, halfb = tid & 1;
        const int m = by*128 + r;
        const int b = m >> 11, s = m & 2047;
        const int h = bx >> 1;
        const int c0 = (bx & 1)*128 + halfb*64;
        __half* dst = Out + ((size_t)((b<<3) + h)*SEQ + s)*256 + c0;
#pragma unroll
        for (int q = 0; q < 8; ++q) {
            uint4 val = lds128a(cs + swz256(r, halfb*128 + q*16));
            *(uint4*)(dst + q*8) = val;
        }
    }
}

// ---------------------------------------------------------------------------
// Output GEMM (f16): BM=64 BN=128 BK=64, grid (2,128).
// ---------------------------------------------------------------------------
#define OB_A 0
#define OB_B 16384
#define OUT_SMEM 49152

__global__ void __launch_bounds__(256) out_kernel(
    const float* __restrict__ bout, float* __restrict__ out)
{
    extern __shared__ __align__(1024) char smc[];
    const uint32_t sb = (uint32_t)__cvta_generic_to_shared(smc);
    const int tid  = threadIdx.x;
    const int lane = tid & 31, warp = tid >> 5;
    const int wm = warp >> 2, wn = warp & 3;
    const int tg = lane & 3, gid = lane >> 2;
    const int lr = lane & 7, lb = (lane >> 3) & 1, lc = lane >> 4;
    const int bx = blockIdx.x, by = blockIdx.y;

    auto loadA = [&](int buf, int kb) {
#pragma unroll
        for (int p = 0; p < 2; ++p) {
            int idx = tid + p*256;
            int r = idx >> 3, cb = (idx & 7) * 16;
            CPA16A(sb + OB_A + (uint32_t)buf*8192 + swz128(r, cb),
                   g_U + (size_t)(by*64 + r)*2048 + kb*64 + (idx & 7)*8);
        }
    };
    auto loadB = [&](int buf, int kb) {
#pragma unroll
        for (int p = 0; p < 4; ++p) {
            int idx = tid + p*256;
            int r = idx >> 4, cb = (idx & 15) * 16;
            CPA16A(sb + OB_B + (uint32_t)buf*16384 + swz256(r, cb),
                   g_Wouth + (size_t)(kb*64 + r)*256 + bx*128 + (idx & 15)*8);
        }
    };

    float acc[2][4][4];
#pragma unroll
    for (int a = 0; a < 2; a++)
#pragma unroll
        for (int b = 0; b < 4; b++)
#pragma unroll
            for (int c = 0; c < 4; c++) acc[a][b][c] = 0.f;

    loadA(0, 0); loadB(0, 0); CP_COMMIT();

    for (int kb = 0; kb < 32; ++kb) {
        const int cur = kb & 1;
        if (kb + 1 < 32) { loadA(cur ^ 1, kb + 1); loadB(cur ^ 1, kb + 1); CP_COMMIT(); }
        if (kb + 1 < 32) { CP_WAIT1(); } else { CP_WAIT0(); }
        __syncthreads();

        const uint32_t abase = sb + OB_A + (uint32_t)cur*8192;
        const uint32_t bbase = sb + OB_B + (uint32_t)cur*16384;
#pragma unroll
        for (int kk = 0; kk < 64; kk += 16) {
            uint32_t A[2][4];
#pragma unroll
            for (int mt = 0; mt < 2; ++mt)
                ldsm4a(A[mt], abase + swz128(wm*32 + mt*16 + lr + lb*8, kk*2 + lc*16));
#pragma unroll
            for (int ntp = 0; ntp < 2; ++ntp) {
                uint32_t B[4];
                ldsm4ta(B, bbase + swz256(kk + lr + lb*8, wn*64 + ntp*32 + lc*16));
                mma16816(acc[0][2*ntp],   A[0][0],A[0][1],A[0][2],A[0][3], B[0],B[1]);
                mma16816(acc[0][2*ntp+1], A[0][0],A[0][1],A[0][2],A[0][3], B[2],B[3]);
                mma16816(acc[1][2*ntp],   A[1][0],A[1][1],A[1][2],A[1][3], B[0],B[1]);
                mma16816(acc[1][2*ntp+1], A[1][0],A[1][1],A[1][2],A[1][3], B[2],B[3]);
            }
        }
        __syncthreads();
    }

#pragma unroll
    for (int mt = 0; mt < 2; ++mt) {
#pragma unroll
        for (int nt = 0; nt < 4; ++nt) {
            int n = bx*128 + wn*32 + nt*8 + 2*tg;
            float2 bb = *(const float2*)(bout + n);
#pragma unroll
            for (int rr = 0; rr < 2; ++rr) {
                int m = by*64 + wm*32 + mt*16 + gid + rr*8;
                float2 res;
                res.x = acc[mt][nt][rr*2]     + bb.x;
                res.y = acc[mt][nt][rr*2 + 1] + bb.y;
                *(float2*)(out + (size_t)m*256 + n) = res;
            }
        }
    }
}

// ---------------------------------------------------------------------------
// Flash attention: 128 q-rows, 256 threads, 1 bar/tile.
// Per tile: [QK-chunk j ; PV(i-1)-chunk j/2 alternating] x8 -> softmax(i).
// smem: Q @0 (64K), K @65536 (2x32K), V @131072 (2x32K), P @196608 (2x16K)
// ---------------------------------------------------------------------------
#define KB_ 65536
#define VB_ 131072
#define PB_ 196608
#define ATTN_SMEM_SZ 229376

__global__ void __launch_bounds__(256, 1) attn_kernel()
{
    extern __shared__ __align__(1024) char smc[];
    const uint32_t sb = (uint32_t)__cvta_generic_to_shared(smc);

    const int tid = threadIdx.x, lane = tid & 31, warp = tid >> 5;
    const int tg = lane & 3, gid = lane >> 2;
    const int lr = lane & 7, lb2 = (lane >> 3) & 1, lc = lane >> 4, l3 = lane >> 3;
    const int wm = warp >> 1, wn = warp & 1;
    const int pm = (warp >> 2) * 64, dn = (warp & 3) * 64;
    const int jr = lane & 15, jc = lane >> 4;

    const int qt = blockIdx.x, bh = blockIdx.y;
    const __half* Qg = g_Q + (size_t)bh*SEQ*256 + (size_t)qt*128*256;
    const __half* Kg = g_K + (size_t)bh*SEQ*256;
    const __half* Vg = g_V + (size_t)bh*SEQ*256;

#pragma unroll
    for (int i = 0; i < 16; ++i) {
        int idx = tid + i*256;
        int m = idx >> 5, cb = (idx & 31) * 16;
        CPA16A(sb + swz512(m, cb), Qg + (size_t)m*256 + (idx & 31)*8);
    }
#pragma unroll
    for (int i = 0; i < 8; ++i) {
        int idx = tid + i*256;
        int n = idx >> 5, cb = (idx & 31) * 16;
        CPA16A(sb + KB_ + swz512(n, cb), Kg + (size_t)n*256 + (idx & 31)*8);
    }
    CP_COMMIT();

    float o[4][8][4];
#pragma unroll
    for (int a = 0; a < 4; ++a)
#pragma unroll
        for (int b = 0; b < 8; ++b)
#pragma unroll
            for (int c = 0; c < 4; ++c) o[a][b][c] = 0.f;
    float ls[2][4];
#pragma unroll
    for (int a = 0; a < 2; ++a)
#pragma unroll
        for (int c = 0; c < 4; ++c) ls[a][c] = 0.f;

    for (int i = 0; i < 32; ++i) {
        const int b = i & 1, pb = b ^ 1;
        CP_WAIT0();
        __syncthreads();

        if (i + 1 < 32) {
            const __half* Kgs = Kg + (size_t)(i+1)*64*256;
#pragma unroll
            for (int j = 0; j < 8; ++j) {
                int idx = tid + j*256;
                int n = idx >> 5, cb = (idx & 31) * 16;
                CPA16A(sb + KB_ + (uint32_t)pb*32768 + swz512(n, cb),
                       Kgs + (size_t)n*256 + (idx & 31)*8);
            }
        }
        {
            const __half* Vgs = Vg + (size_t)i*64*256;
#pragma unroll
            for (int j = 0; j < 8; ++j) {
                int idx = tid + j*256;
                int n = idx >> 5, cb = (idx & 31) * 16;
                CPA16A(sb + VB_ + (uint32_t)b*32768 + swz512(n, cb),
                       Vgs + (size_t)n*256 + (idx & 31)*8);
            }
        }
        CP_COMMIT();

        float s[2][4][4];
#pragma unroll
        for (int a = 0; a < 2; ++a)
#pragma unroll
            for (int bq = 0; bq < 4; ++bq)
#pragma unroll
                for (int c = 0; c < 4; ++c) s[a][bq][c] = 0.f;

        const uint32_t kbase = sb + KB_ + (uint32_t)b*32768;
        const uint32_t vbase = sb + VB_ + (uint32_t)pb*32768;
        const uint32_t pbase = sb + PB_ + (uint32_t)pb*16384;

        // ---- fused: QK(i) chunk j interleaved with PV(i-1) chunk j>>1 ----
#pragma unroll
        for (int j = 0; j < 8; ++j) {
            {   // QK chunk j (k columns j*32 .. j*32+31)
                const int k0b = j * 64;
                uint32_t A[2][2][4];
#pragma unroll
                for (int mt = 0; mt < 2; ++mt) {
                    const int rowA = wm*32 + mt*16 + lr + lb2*8;
                    ldsm4a(A[mt][0], sb + swz512(rowA, k0b + lc*16));
                    ldsm4a(A[mt][1], sb + swz512(rowA, k0b + 32 + lc*16));
                }
#pragma unroll
                for (int nt = 0; nt < 4; ++nt) {
                    uint32_t B[4];
                    ldsm4a(B, kbase + swz512(wn*32 + nt*8 + lr, k0b + l3*16));
#pragma unroll
                    for (int mt = 0; mt < 2; ++mt) {
                        mma16816(s[mt][nt], A[mt][0][0],A[mt][0][1],A[mt][0][2],A[mt][0][3], B[0],B[1]);
                        mma16816(s[mt][nt], A[mt][1][0],A[mt][1][1],A[mt][1][2],A[mt][1][3], B[2],B[3]);
                    }
                }
            }
            if ((i > 0) && (j & 1)) {   // PV chunk kk = j>>1
                const int kk = j >> 1;
                uint32_t Bv[4][4];
#pragma unroll
                for (int nt2 = 0; nt2 < 4; ++nt2)
                    ldsm4ta(Bv[nt2], vbase + swz512(kk*16 + lr + lb2*8,
                                                    dn*2 + nt2*32 + lc*16));
#pragma unroll
                for (int mt2 = 0; mt2 < 4; ++mt2) {
                    uint32_t Ap[4];
                    ldsm4a(Ap, pbase + swz128(pm + mt2*16 + lr + lb2*8, kk*32 + lc*16));
#pragma unroll
                    for (int nt2 = 0; nt2 < 4; ++nt2) {
                        mma16816(o[mt2][2*nt2],   Ap[0],Ap[1],Ap[2],Ap[3], Bv[nt2][0],Bv[nt2][1]);
                        mma16816(o[mt2][2*nt2+1], Ap[0],Ap[1],Ap[2],Ap[3], Bv[nt2][2],Bv[nt2][3]);
                    }
                }
            }
        }

        // ---- softmax(i): P->smem + l-MMA ----
        {
            const uint32_t pw = sb + PB_ + (uint32_t)b*16384;
#pragma unroll
            for (int mt = 0; mt < 2; ++mt) {
#pragma unroll
                for (int ntp = 0; ntp < 2; ++ntp) {
                    uint32_t x[2][2];
#pragma unroll
                    for (int h2 = 0; h2 < 2; ++h2) {
                        const int nt = 2*ntp + h2;
                        x[h2][0] = pack_ex2(s[mt][nt][0], s[mt][nt][1]);
                        x[h2][1] = pack_ex2(s[mt][nt][2], s[mt][nt][3]);
                    }
                    stsm4a(pw + swz128(wm*32 + mt*16 + jr, wn*64 + ntp*32 + jc*16),
                           x[0][0], x[0][1], x[1][0], x[1][1]);
                    mma16816(ls[mt], x[0][0], x[0][1], x[1][0], x[1][1], ONES2, ONES2);
                }
            }
        }
    }

    // tail: PV(31)
    CP_WAIT0();
    __syncthreads();
    {
        const uint32_t vbase = sb + VB_ + 32768;
        const uint32_t pbase = sb + PB_ + 16384;
#pragma unroll
        for (int kk = 0; kk < 4; ++kk) {
            uint32_t Bv[4][4];
#pragma unroll
            for (int nt2 = 0; nt2 < 4; ++nt2)
                ldsm4ta(Bv[nt2], vbase + swz512(kk*16 + lr + lb2*8,
                                                dn*2 + nt2*32 + lc*16));
#pragma unroll
            for (int mt2 = 0; mt2 < 4; ++mt2) {
                uint32_t Ap[4];
                ldsm4a(Ap, pbase + swz128(pm + mt2*16 + lr + lb2*8, kk*32 + lc*16));
#pragma unroll
                for (int nt2 = 0; nt2 < 4; ++nt2) {
                    mma16816(o[mt2][2*nt2],   Ap[0],Ap[1],Ap[2],Ap[3], Bv[nt2][0],Bv[nt2][1]);
                    mma16816(o[mt2][2*nt2+1], Ap[0],Ap[1],Ap[2],Ap[3], Bv[nt2][2],Bv[nt2][3]);
                }
            }
        }
    }

    // l publish
    float* Lp = (float*)(smc + PB_);
    __syncthreads();
    if (tg == 0) {
#pragma unroll
        for (int mt = 0; mt < 2; ++mt) {
            Lp[(wm*32 + mt*16 + gid)*2 + wn]     = ls[mt][0];
            Lp[(wm*32 + mt*16 + gid + 8)*2 + wn] = ls[mt][2];
        }
    }
    __syncthreads();

    const int bB = bh >> 3, h = bh & 7;
    __half* Ub = g_U + ((size_t)(bB*SEQ + qt*128))*NQK + h*256;
#pragma unroll
    for (int mt2 = 0; mt2 < 4; ++mt2) {
        const int r0 = pm + mt2*16 + gid;
        const float linv0 = 1.f / (Lp[r0*2] + Lp[r0*2+1]);
        const float linv1 = 1.f / (Lp[(r0+8)*2] + Lp[(r0+8)*2+1]);
        __half* u0 = Ub + (size_t)r0*NQK + dn;
        __half* u1 = Ub + (size_t)(r0+8)*NQK + dn;
#pragma unroll
        for (int nt = 0; nt < 8; ++nt) {
            const int c = nt*8 + 2*tg;
            *(__half2*)(u0 + c) = __floats2half2_rn(o[mt2][nt][0]*linv0, o[mt2][nt][1]*linv0);
            *(__half2*)(u1 + c) = __floats2half2_rn(o[mt2][nt][2]*linv1, o[mt2][nt][3]*linv1);
        }
    }
}

// ---------------------------------------------------------------------------
extern "C" void kernel_launch(void* const* d_in, const int* in_sizes, int n_in,
                              void* d_out, int out_size)
{
    (void)in_sizes; (void)n_in; (void)out_size;
    const float* v    = (const float*)d_in[0];
    const float* WQ   = (const float*)d_in[1];
    const float* WK   = (const float*)d_in[2];
    const float* WV   = (const float*)d_in[3];
    const float* Wout = (const float*)d_in[4];
    const float* bout = (const float*)d_in[5];
    float* out = (float*)d_out;

    cvt_all_kernel<<<(CVT_TOTAL + 255)/256, 256>>>(
        (const float4*)v, (const float4*)WQ, (const float4*)WK,
        (const float4*)WV, (const float4*)Wout);

    cudaFuncSetAttribute(proj_kernel,
                         cudaFuncAttributeMaxDynamicSharedMemorySize, GEMM_SMEM);
    proj_kernel<<<dim3(16, 64, 3), 256, GEMM_SMEM>>>();

    cudaFuncSetAttribute(attn_kernel,
                         cudaFuncAttributeMaxDynamicSharedMemorySize, ATTN_SMEM_SZ);
    attn_kernel<<<dim3(16, 32), 256, ATTN_SMEM_SZ>>>();

    cudaFuncSetAttribute(out_kernel,
                         cudaFuncAttributeMaxDynamicSharedMemorySize, OUT_SMEM);
    out_kernel<<<dim3(2, 128), 256, OUT_SMEM>>>(bout, out);
}

// round 16
// speedup vs baseline: 1.0127x; 1.0127x over previous
#include <cuda_runtime.h>
#include <cuda_fp16.h>
#include <cstdint>

// ---------------------------------------------------------------------------
// SelfAttention: B=4, S=2048, IN_C=256, HEADS=8, head_dim=256, HID_C=256
// R16: attn reverted to R14 (best measured). out_kernel BK 64->128 (halves
// barrier count; 16 K-iters). proj/cvt unchanged from R14.
// ---------------------------------------------------------------------------

#define BATCH 4
#define SEQ   2048
#define INC   256
#define HEADS 8
#define NQK   (INC*HEADS)
#define ROWS_TOTAL (BATCH*SEQ)
#define SM_SCALE 0.17677669529663687f
#define LOG2E    1.4426950408889634f
#define CCF      (SM_SCALE*LOG2E)
#define ONES2    0x3C003C00u           // half2(1,1)

__device__ __half g_Q[(size_t)BATCH*HEADS*SEQ*INC];
__device__ __half g_K[(size_t)BATCH*HEADS*SEQ*INC];
__device__ __half g_V[(size_t)BATCH*HEADS*SEQ*INC];
__device__ __half g_U[(size_t)ROWS_TOTAL*NQK];
__device__ __half g_Xh[(size_t)ROWS_TOTAL*INC];
__device__ __half g_WQh[(size_t)INC*NQK];
__device__ __half g_WKh[(size_t)INC*NQK];
__device__ __half g_WVh[(size_t)INC*NQK];
__device__ __half g_Wouth[(size_t)NQK*INC];

__device__ __forceinline__ void mma16816(float c[4],
    uint32_t a0, uint32_t a1, uint32_t a2, uint32_t a3,
    uint32_t b0, uint32_t b1)
{
    asm volatile(
        "mma.sync.aligned.m16n8k16.row.col.f32.f16.f16.f32 "
        "{%0,%1,%2,%3}, {%4,%5,%6,%7}, {%8,%9}, {%0,%1,%2,%3};\n"
        : "+f"(c[0]), "+f"(c[1]), "+f"(c[2]), "+f"(c[3])
        : "r"(a0), "r"(a1), "r"(a2), "r"(a3), "r"(b0), "r"(b1));
}
__device__ __forceinline__ void ldsm4a(uint32_t r[4], uint32_t a) {
    asm volatile("ldmatrix.sync.aligned.m8n8.x4.shared.b16 {%0,%1,%2,%3}, [%4];"
        : "=r"(r[0]), "=r"(r[1]), "=r"(r[2]), "=r"(r[3]) : "r"(a));
}
__device__ __forceinline__ void ldsm4ta(uint32_t r[4], uint32_t a) {
    asm volatile("ldmatrix.sync.aligned.m8n8.x4.trans.shared.b16 {%0,%1,%2,%3}, [%4];"
        : "=r"(r[0]), "=r"(r[1]), "=r"(r[2]), "=r"(r[3]) : "r"(a));
}
__device__ __forceinline__ void stsm4a(uint32_t a, uint32_t r0, uint32_t r1,
                                       uint32_t r2, uint32_t r3) {
    asm volatile("stmatrix.sync.aligned.m8n8.x4.shared.b16 [%0], {%1,%2,%3,%4};"
        :: "r"(a), "r"(r0), "r"(r1), "r"(r2), "r"(r3) : "memory");
}
__device__ __forceinline__ uint32_t pack_ex2(float a, float b) {
    __half2 h = __floats2half2_rn(a, b);
    uint32_t u = reinterpret_cast<uint32_t&>(h);
    asm volatile("ex2.approx.f16x2 %0, %0;" : "+r"(u));
    return u;
}
__device__ __forceinline__ uint32_t packh2(float a, float b) {
    __half2 h = __floats2half2_rn(a, b);
    return reinterpret_cast<uint32_t&>(h);
}
__device__ __forceinline__ uint4 lds128a(uint32_t a) {
    uint4 v;
    asm volatile("ld.shared.v4.b32 {%0,%1,%2,%3}, [%4];"
        : "=r"(v.x), "=r"(v.y), "=r"(v.z), "=r"(v.w) : "r"(a));
    return v;
}

#define CPA16A(dsta, src) \
    asm volatile("cp.async.cg.shared.global [%0], [%1], 16;" :: "r"(dsta), "l"(src))
#define CP_COMMIT() asm volatile("cp.async.commit_group;")
#define CP_WAIT0()  asm volatile("cp.async.wait_group 0;")
#define CP_WAIT1()  asm volatile("cp.async.wait_group 1;")

__device__ __forceinline__ uint32_t swz512(int row, int cb) {
    return (uint32_t)(row*512 + (cb ^ ((row & 7) << 4)));
}
__device__ __forceinline__ uint32_t swz256(int row, int cb) {
    return (uint32_t)(row*256 + (cb ^ ((row & 7) << 4)));
}
__device__ __forceinline__ uint32_t swz128(int row, int cb) {
    return (uint32_t)(row*128 + (cb ^ ((row & 7) << 4)));
}

// ---------------------------------------------------------------------------
// Fused f32 -> f16 convert for all 5 tensors
// ---------------------------------------------------------------------------
#define CVT_NX   (ROWS_TOTAL*INC/8)
#define CVT_NW   (INC*NQK/8)
#define CVT_TOTAL (CVT_NX + 4*CVT_NW)

__global__ void __launch_bounds__(256) cvt_all_kernel(
    const float4* __restrict__ v,  const float4* __restrict__ wq,
    const float4* __restrict__ wk, const float4* __restrict__ wv,
    const float4* __restrict__ wo)
{
    int i = blockIdx.x * 256 + threadIdx.x;
    if (i >= CVT_TOTAL) return;
    const float4* src; uint4* dst; int off;
    if (i < CVT_NX)               { src = v;  dst = (uint4*)g_Xh;    off = i; }
    else if (i < CVT_NX+CVT_NW)   { src = wq; dst = (uint4*)g_WQh;   off = i - CVT_NX; }
    else if (i < CVT_NX+2*CVT_NW) { src = wk; dst = (uint4*)g_WKh;   off = i - CVT_NX - CVT_NW; }
    else if (i < CVT_NX+3*CVT_NW) { src = wv; dst = (uint4*)g_WVh;   off = i - CVT_NX - 2*CVT_NW; }
    else                          { src = wo; dst = (uint4*)g_Wouth; off = i - CVT_NX - 3*CVT_NW; }
    float4 a = src[2*off], b = src[2*off+1];
    uint4 o;
    o.x = packh2(a.x, a.y); o.y = packh2(a.z, a.w);
    o.z = packh2(b.x, b.y); o.w = packh2(b.z, b.w);
    dst[off] = o;
}

// ---------------------------------------------------------------------------
// Projection GEMM (f16): BM=128 BN=128 BK=64, double-buffered.
// Epilogue: stmatrix-stage C in smem, coalesced uint4 writes.
// ---------------------------------------------------------------------------
#define GB_A 0
#define GB_B 32768
#define GEMM_SMEM 65536

__global__ void __launch_bounds__(256) proj_kernel()
{
    extern __shared__ __align__(1024) char smc[];
    const uint32_t sb = (uint32_t)__cvta_generic_to_shared(smc);
    const int tid  = threadIdx.x;
    const int lane = tid & 31, warp = tid >> 5;
    const int wm = warp >> 1, wn = warp & 1;
    const int lr = lane & 7, lb = (lane >> 3) & 1, lc = lane >> 4;
    const int jr = lane & 15, jc = lane >> 4;
    const int bx = blockIdx.x, by = blockIdx.y, which = blockIdx.z;
    const __half* W = (which == 0) ? g_WQh : (which == 1) ? g_WKh : g_WVh;
    const __half* X = g_Xh;

    auto loadA = [&](int buf, int kb) {
#pragma unroll
        for (int p = 0; p < 4; ++p) {
            int idx = tid + p*256;
            int r = idx >> 3, cb = (idx & 7) * 16;
            CPA16A(sb + GB_A + (uint32_t)buf*16384 + swz128(r, cb),
                   X + (size_t)(by*128 + r)*256 + kb*64 + (idx & 7)*8);
        }
    };
    auto loadB = [&](int buf, int kb) {
#pragma unroll
        for (int p = 0; p < 4; ++p) {
            int idx = tid + p*256;
            int r = idx >> 4, cb = (idx & 15) * 16;
            CPA16A(sb + GB_B + (uint32_t)buf*16384 + swz256(r, cb),
                   W + (size_t)(kb*64 + r)*2048 + bx*128 + (idx & 15)*8);
        }
    };

    float acc[2][8][4];
#pragma unroll
    for (int a = 0; a < 2; a++)
#pragma unroll
        for (int b = 0; b < 8; b++)
#pragma unroll
            for (int c = 0; c < 4; c++) acc[a][b][c] = 0.f;

    loadA(0, 0); loadB(0, 0); CP_COMMIT();

    for (int kb = 0; kb < 4; ++kb) {
        const int cur = kb & 1;
        if (kb + 1 < 4) { loadA(cur ^ 1, kb + 1); loadB(cur ^ 1, kb + 1); CP_COMMIT(); }
        if (kb + 1 < 4) { CP_WAIT1(); } else { CP_WAIT0(); }
        __syncthreads();

        const uint32_t abase = sb + GB_A + (uint32_t)cur*16384;
        const uint32_t bbase = sb + GB_B + (uint32_t)cur*16384;
#pragma unroll
        for (int kk = 0; kk < 64; kk += 16) {
            uint32_t A[2][4];
#pragma unroll
            for (int mt = 0; mt < 2; ++mt)
                ldsm4a(A[mt], abase + swz128(wm*32 + mt*16 + lr + lb*8, kk*2 + lc*16));
#pragma unroll
            for (int ntp = 0; ntp < 4; ++ntp) {
                uint32_t B[4];
                ldsm4ta(B, bbase + swz256(kk + lr + lb*8, wn*128 + ntp*32 + lc*16));
                mma16816(acc[0][2*ntp],   A[0][0],A[0][1],A[0][2],A[0][3], B[0],B[1]);
                mma16816(acc[0][2*ntp+1], A[0][0],A[0][1],A[0][2],A[0][3], B[2],B[3]);
                mma16816(acc[1][2*ntp],   A[1][0],A[1][1],A[1][2],A[1][3], B[0],B[1]);
                mma16816(acc[1][2*ntp+1], A[1][0],A[1][1],A[1][2],A[1][3], B[2],B[3]);
            }
        }
        __syncthreads();
    }

    const float sc = (which == 0) ? CCF : 1.f;
    const uint32_t cs = sb + GB_A;
#pragma unroll
    for (int mt = 0; mt < 2; ++mt) {
#pragma unroll
        for (int ntp = 0; ntp < 4; ++ntp) {
            uint32_t e01 = packh2(acc[mt][2*ntp][0]*sc,   acc[mt][2*ntp][1]*sc);
            uint32_t e23 = packh2(acc[mt][2*ntp][2]*sc,   acc[mt][2*ntp][3]*sc);
            uint32_t o01 = packh2(acc[mt][2*ntp+1][0]*sc, acc[mt][2*ntp+1][1]*sc);
            uint32_t o23 = packh2(acc[mt][2*ntp+1][2]*sc, acc[mt][2*ntp+1][3]*sc);
            stsm4a(cs + swz256(wm*32 + mt*16 + jr, wn*128 + ntp*32 + jc*16),
                   e01, e23, o01, o23);
        }
    }
    __syncthreads();

    __half* Out = (which == 0) ? g_Q : (which == 1) ? g_K : g_V;
    {
        const int r = tid >> 1, halfb = tid & 1;
        const int m = by*128 + r;
        const int b = m >> 11, s = m & 2047;
        const int h = bx >> 1;
        const int c0 = (bx & 1)*128 + halfb*64;
        __half* dst = Out + ((size_t)((b<<3) + h)*SEQ + s)*256 + c0;
#pragma unroll
        for (int q = 0; q < 8; ++q) {
            uint4 val = lds128a(cs + swz256(r, halfb*128 + q*16));
            *(uint4*)(dst + q*8) = val;
        }
    }
}

// ---------------------------------------------------------------------------
// Output GEMM (f16): BM=64 BN=128 BK=128, grid (2,128), 16 K-iters.
// smem: A 2x16K (64x256B rows), B 2x32K (128x256B rows) = 96K.
// ---------------------------------------------------------------------------
#define OB_A 0
#define OB_B 32768
#define OUT_SMEM 98304

__global__ void __launch_bounds__(256) out_kernel(
    const float* __restrict__ bout, float* __restrict__ out)
{
    extern __shared__ __align__(1024) char smc[];
    const uint32_t sb = (uint32_t)__cvta_generic_to_shared(smc);
    const int tid  = threadIdx.x;
    const int lane = tid & 31, warp = tid >> 5;
    const int wm = warp >> 2, wn = warp & 3;
    const int tg = lane & 3, gid = lane >> 2;
    const int lr = lane & 7, lb = (lane >> 3) & 1, lc = lane >> 4;
    const int bx = blockIdx.x, by = blockIdx.y;

    auto loadA = [&](int buf, int kb) {
#pragma unroll
        for (int p = 0; p < 4; ++p) {
            int idx = tid + p*256;
            int r = idx >> 4, cb = (idx & 15) * 16;
            CPA16A(sb + OB_A + (uint32_t)buf*16384 + swz256(r, cb),
                   g_U + (size_t)(by*64 + r)*2048 + kb*128 + (idx & 15)*8);
        }
    };
    auto loadB = [&](int buf, int kb) {
#pragma unroll
        for (int p = 0; p < 8; ++p) {
            int idx = tid + p*256;
            int r = idx >> 4, cb = (idx & 15) * 16;
            CPA16A(sb + OB_B + (uint32_t)buf*32768 + swz256(r, cb),
                   g_Wouth + (size_t)(kb*128 + r)*256 + bx*128 + (idx & 15)*8);
        }
    };

    float acc[2][4][4];
#pragma unroll
    for (int a = 0; a < 2; a++)
#pragma unroll
        for (int b = 0; b < 4; b++)
#pragma unroll
            for (int c = 0; c < 4; c++) acc[a][b][c] = 0.f;

    loadA(0, 0); loadB(0, 0); CP_COMMIT();

    for (int kb = 0; kb < 16; ++kb) {
        const int cur = kb & 1;
        if (kb + 1 < 16) { loadA(cur ^ 1, kb + 1); loadB(cur ^ 1, kb + 1); CP_COMMIT(); }
        if (kb + 1 < 16) { CP_WAIT1(); } else { CP_WAIT0(); }
        __syncthreads();

        const uint32_t abase = sb + OB_A + (uint32_t)cur*16384;
        const uint32_t bbase = sb + OB_B + (uint32_t)cur*32768;
#pragma unroll
        for (int kk = 0; kk < 128; kk += 16) {
            uint32_t A[2][4];
#pragma unroll
            for (int mt = 0; mt < 2; ++mt)
                ldsm4a(A[mt], abase + swz256(wm*32 + mt*16 + lr + lb*8, kk*2 + lc*16));
#pragma unroll
            for (int ntp = 0; ntp < 2; ++ntp) {
                uint32_t B[4];
                ldsm4ta(B, bbase + swz256(kk + lr + lb*8, wn*64 + ntp*32 + lc*16));
                mma16816(acc[0][2*ntp],   A[0][0],A[0][1],A[0][2],A[0][3], B[0],B[1]);
                mma16816(acc[0][2*ntp+1], A[0][0],A[0][1],A[0][2],A[0][3], B[2],B[3]);
                mma16816(acc[1][2*ntp],   A[1][0],A[1][1],A[1][2],A[1][3], B[0],B[1]);
                mma16816(acc[1][2*ntp+1], A[1][0],A[1][1],A[1][2],A[1][3], B[2],B[3]);
            }
        }
        __syncthreads();
    }

#pragma unroll
    for (int mt = 0; mt < 2; ++mt) {
#pragma unroll
        for (int nt = 0; nt < 4; ++nt) {
            int n = bx*128 + wn*32 + nt*8 + 2*tg;
            float2 bb = *(const float2*)(bout + n);
#pragma unroll
            for (int rr = 0; rr < 2; ++rr) {
                int m = by*64 + wm*32 + mt*16 + gid + rr*8;
                float2 res;
                res.x = acc[mt][nt][rr*2]     + bb.x;
                res.y = acc[mt][nt][rr*2 + 1] + bb.y;
                *(float2*)(out + (size_t)m*256 + n) = res;
            }
        }
    }
}

// ---------------------------------------------------------------------------
// Flash attention (R14 best): 128 q-rows, 256 threads, 1 bar/tile.
// Per tile: QK -> softmax -> PV(i-1).
// smem: Q @0 (64K), K @65536 (2x32K), V @131072 (2x32K), P @196608 (2x16K)
// ---------------------------------------------------------------------------
#define KB_ 65536
#define VB_ 131072
#define PB_ 196608
#define ATTN_SMEM_SZ 229376

__global__ void __launch_bounds__(256, 1) attn_kernel()
{
    extern __shared__ __align__(1024) char smc[];
    const uint32_t sb = (uint32_t)__cvta_generic_to_shared(smc);

    const int tid = threadIdx.x, lane = tid & 31, warp = tid >> 5;
    const int tg = lane & 3, gid = lane >> 2;
    const int lr = lane & 7, lb2 = (lane >> 3) & 1, lc = lane >> 4, l3 = lane >> 3;
    const int wm = warp >> 1, wn = warp & 1;
    const int pm = (warp >> 2) * 64, dn = (warp & 3) * 64;
    const int jr = lane & 15, jc = lane >> 4;

    const int qt = blockIdx.x, bh = blockIdx.y;
    const __half* Qg = g_Q + (size_t)bh*SEQ*256 + (size_t)qt*128*256;
    const __half* Kg = g_K + (size_t)bh*SEQ*256;
    const __half* Vg = g_V + (size_t)bh*SEQ*256;

#pragma unroll
    for (int i = 0; i < 16; ++i) {
        int idx = tid + i*256;
        int m = idx >> 5, cb = (idx & 31) * 16;
        CPA16A(sb + swz512(m, cb), Qg + (size_t)m*256 + (idx & 31)*8);
    }
#pragma unroll
    for (int i = 0; i < 8; ++i) {
        int idx = tid + i*256;
        int n = idx >> 5, cb = (idx & 31) * 16;
        CPA16A(sb + KB_ + swz512(n, cb), Kg + (size_t)n*256 + (idx & 31)*8);
    }
    CP_COMMIT();

    float o[4][8][4];
#pragma unroll
    for (int a = 0; a < 4; ++a)
#pragma unroll
        for (int b = 0; b < 8; ++b)
#pragma unroll
            for (int c = 0; c < 4; ++c) o[a][b][c] = 0.f;
    float ls[2][4];
#pragma unroll
    for (int a = 0; a < 2; ++a)
#pragma unroll
        for (int c = 0; c < 4; ++c) ls[a][c] = 0.f;

    for (int i = 0; i < 32; ++i) {
        const int b = i & 1, pb = b ^ 1;
        CP_WAIT0();
        __syncthreads();

        if (i + 1 < 32) {
            const __half* Kgs = Kg + (size_t)(i+1)*64*256;
#pragma unroll
            for (int j = 0; j < 8; ++j) {
                int idx = tid + j*256;
                int n = idx >> 5, cb = (idx & 31) * 16;
                CPA16A(sb + KB_ + (uint32_t)pb*32768 + swz512(n, cb),
                       Kgs + (size_t)n*256 + (idx & 31)*8);
            }
        }
        {
            const __half* Vgs = Vg + (size_t)i*64*256;
#pragma unroll
            for (int j = 0; j < 8; ++j) {
                int idx = tid + j*256;
                int n = idx >> 5, cb = (idx & 31) * 16;
                CPA16A(sb + VB_ + (uint32_t)b*32768 + swz512(n, cb),
                       Vgs + (size_t)n*256 + (idx & 31)*8);
            }
        }
        CP_COMMIT();

        float s[2][4][4];
#pragma unroll
        for (int a = 0; a < 2; ++a)
#pragma unroll
            for (int bq = 0; bq < 4; ++bq)
#pragma unroll
                for (int c = 0; c < 4; ++c) s[a][bq][c] = 0.f;

        const uint32_t kbase = sb + KB_ + (uint32_t)b*32768;
#pragma unroll
        for (int kc = 0; kc < 8; ++kc) {
            const int k0b = kc * 64;
            uint32_t A[2][2][4];
#pragma unroll
            for (int mt = 0; mt < 2; ++mt) {
                const int rowA = wm*32 + mt*16 + lr + lb2*8;
                ldsm4a(A[mt][0], sb + swz512(rowA, k0b + lc*16));
                ldsm4a(A[mt][1], sb + swz512(rowA, k0b + 32 + lc*16));
            }
#pragma unroll
            for (int nt = 0; nt < 4; ++nt) {
                uint32_t B[4];
                ldsm4a(B, kbase + swz512(wn*32 + nt*8 + lr, k0b + l3*16));
#pragma unroll
                for (int mt = 0; mt < 2; ++mt) {
                    mma16816(s[mt][nt], A[mt][0][0],A[mt][0][1],A[mt][0][2],A[mt][0][3], B[0],B[1]);
                    mma16816(s[mt][nt], A[mt][1][0],A[mt][1][1],A[mt][1][2],A[mt][1][3], B[2],B[3]);
                }
            }
        }

        // softmax(i): P->smem + l-MMA
        {
            const uint32_t pw = sb + PB_ + (uint32_t)b*16384;
#pragma unroll
            for (int mt = 0; mt < 2; ++mt) {
#pragma unroll
                for (int ntp = 0; ntp < 2; ++ntp) {
                    uint32_t x[2][2];
#pragma unroll
                    for (int h2 = 0; h2 < 2; ++h2) {
                        const int nt = 2*ntp + h2;
                        x[h2][0] = pack_ex2(s[mt][nt][0], s[mt][nt][1]);
                        x[h2][1] = pack_ex2(s[mt][nt][2], s[mt][nt][3]);
                    }
                    stsm4a(pw + swz128(wm*32 + mt*16 + jr, wn*64 + ntp*32 + jc*16),
                           x[0][0], x[0][1], x[1][0], x[1][1]);
                    mma16816(ls[mt], x[0][0], x[0][1], x[1][0], x[1][1], ONES2, ONES2);
                }
            }
        }

        // PV(i-1)
        if (i > 0) {
            const uint32_t vbase = sb + VB_ + (uint32_t)pb*32768;
            const uint32_t pbase = sb + PB_ + (uint32_t)pb*16384;
#pragma unroll
            for (int kk = 0; kk < 4; ++kk) {
                uint32_t Bv[4][4];
#pragma unroll
                for (int nt2 = 0; nt2 < 4; ++nt2)
                    ldsm4ta(Bv[nt2], vbase + swz512(kk*16 + lr + lb2*8,
                                                    dn*2 + nt2*32 + lc*16));
#pragma unroll
                for (int mt2 = 0; mt2 < 4; ++mt2) {
                    uint32_t Ap[4];
                    ldsm4a(Ap, pbase + swz128(pm + mt2*16 + lr + lb2*8, kk*32 + lc*16));
#pragma unroll
                    for (int nt2 = 0; nt2 < 4; ++nt2) {
                        mma16816(o[mt2][2*nt2],   Ap[0],Ap[1],Ap[2],Ap[3], Bv[nt2][0],Bv[nt2][1]);
                        mma16816(o[mt2][2*nt2+1], Ap[0],Ap[1],Ap[2],Ap[3], Bv[nt2][2],Bv[nt2][3]);
                    }
                }
            }
        }
    }

    // tail: PV(31)
    CP_WAIT0();
    __syncthreads();
    {
        const uint32_t vbase = sb + VB_ + 32768;
        const uint32_t pbase = sb + PB_ + 16384;
#pragma unroll
        for (int kk = 0; kk < 4; ++kk) {
            uint32_t Bv[4][4];
#pragma unroll
            for (int nt2 = 0; nt2 < 4; ++nt2)
                ldsm4ta(Bv[nt2], vbase + swz512(kk*16 + lr + lb2*8,
                                                dn*2 + nt2*32 + lc*16));
#pragma unroll
            for (int mt2 = 0; mt2 < 4; ++mt2) {
                uint32_t Ap[4];
                ldsm4a(Ap, pbase + swz128(pm + mt2*16 + lr + lb2*8, kk*32 + lc*16));
#pragma unroll
                for (int nt2 = 0; nt2 < 4; ++nt2) {
                    mma16816(o[mt2][2*nt2],   Ap[0],Ap[1],Ap[2],Ap[3], Bv[nt2][0],Bv[nt2][1]);
                    mma16816(o[mt2][2*nt2+1], Ap[0],Ap[1],Ap[2],Ap[3], Bv[nt2][2],Bv[nt2][3]);
                }
            }
        }
    }

    // l publish
    float* Lp = (float*)(smc + PB_);
    __syncthreads();
    if (tg == 0) {
#pragma unroll
        for (int mt = 0; mt < 2; ++mt) {
            Lp[(wm*32 + mt*16 + gid)*2 + wn]     = ls[mt][0];
            Lp[(wm*32 + mt*16 + gid + 8)*2 + wn] = ls[mt][2];
        }
    }
    __syncthreads();

    const int bB = bh >> 3, h = bh & 7;
    __half* Ub = g_U + ((size_t)(bB*SEQ + qt*128))*NQK + h*256;
#pragma unroll
    for (int mt2 = 0; mt2 < 4; ++mt2) {
        const int r0 = pm + mt2*16 + gid;
        const float linv0 = 1.f / (Lp[r0*2] + Lp[r0*2+1]);
        const float linv1 = 1.f / (Lp[(r0+8)*2] + Lp[(r0+8)*2+1]);
        __half* u0 = Ub + (size_t)r0*NQK + dn;
        __half* u1 = Ub + (size_t)(r0+8)*NQK + dn;
#pragma unroll
        for (int nt = 0; nt < 8; ++nt) {
            const int c = nt*8 + 2*tg;
            *(__half2*)(u0 + c) = __floats2half2_rn(o[mt2][nt][0]*linv0, o[mt2][nt][1]*linv0);
            *(__half2*)(u1 + c) = __floats2half2_rn(o[mt2][nt][2]*linv1, o[mt2][nt][3]*linv1);
        }
    }
}

// ---------------------------------------------------------------------------
extern "C" void kernel_launch(void* const* d_in, const int* in_sizes, int n_in,
                              void* d_out, int out_size)
{
    (void)in_sizes; (void)n_in; (void)out_size;
    const float* v    = (const float*)d_in[0];
    const float* WQ   = (const float*)d_in[1];
    const float* WK   = (const float*)d_in[2];
    const float* WV   = (const float*)d_in[3];
    const float* Wout = (const float*)d_in[4];
    const float* bout = (const float*)d_in[5];
    float* out = (float*)d_out;

    cvt_all_kernel<<<(CVT_TOTAL + 255)/256, 256>>>(
        (const float4*)v, (const float4*)WQ, (const float4*)WK,
        (const float4*)WV, (const float4*)Wout);

    cudaFuncSetAttribute(proj_kernel,
                         cudaFuncAttributeMaxDynamicSharedMemorySize, GEMM_SMEM);
    proj_kernel<<<dim3(16, 64, 3), 256, GEMM_SMEM>>>();

    cudaFuncSetAttribute(attn_kernel,
                         cudaFuncAttributeMaxDynamicSharedMemorySize, ATTN_SMEM_SZ);
    attn_kernel<<<dim3(16, 32), 256, ATTN_SMEM_SZ>>>();

    cudaFuncSetAttribute(out_kernel,
                         cudaFuncAttributeMaxDynamicSharedMemorySize, OUT_SMEM);
    out_kernel<<<dim3(2, 128), 256, OUT_SMEM>>>(bout, out);
}